// round 1
// baseline (speedup 1.0000x reference)
#include <cuda_runtime.h>
#include <math.h>
#include <float.h>

#define T_STEPS 32
#define B_SZ    512
#define S_SZ    64
#define F_IN    128
#define H1      256
#define H2      256
#define H3      128
#define M_ROWS  (T_STEPS * B_SZ)   // 16384

// Scratch (allocation-free rule: __device__ globals)
__device__ float g_spk0[T_STEPS * B_SZ * F_IN];   // 8 MB encoded spikes (mean over S)
__device__ float g_cur [T_STEPS * B_SZ * H1];     // 16 MB, reused per layer
__device__ float g_spk1[T_STEPS * B_SZ * H1];     // 16 MB
__device__ float g_spk2[T_STEPS * B_SZ * H2];     // 16 MB

// ---------------------------------------------------------------------------
// Latency encode + mean over S.
// Block = one batch element b (512 blocks), thread = one feature f (128 thr).
// For each (b,f): gate x<0.75 -> 0, min/max over s, per-s spike time t_idx,
// histogram over T into shared, write counts/64 to (T,B,F).
// ---------------------------------------------------------------------------
__global__ void encode_kernel(const float* __restrict__ x, float* __restrict__ out) {
    int b = blockIdx.x;
    int f = threadIdx.x;
    __shared__ float cnt[T_STEPS * F_IN];   // 16 KB, column f owned by thread f
#pragma unroll
    for (int t = 0; t < T_STEPS; ++t) cnt[t * F_IN + f] = 0.f;

    const float* xb = x + (size_t)b * S_SZ * F_IN + f;

    float vmin = FLT_MAX, vmax = -FLT_MAX;
#pragma unroll 8
    for (int s = 0; s < S_SZ; ++s) {
        float v = xb[s * F_IN];
        v = (v < 0.75f) ? 0.f : v;          // ENC_THR gate
        vmin = fminf(vmin, v);
        vmax = fmaxf(vmax, v);
    }
    float denom = vmax - vmin + 1e-8f;

    const float c1   = 0.0100001f;                     // float(LAT_THR + EPS)
    const float tmax = 11.512935464920229f;            // float(log((0.01+1e-7)/1e-7))

#pragma unroll 4
    for (int s = 0; s < S_SZ; ++s) {
        float v = xb[s * F_IN];
        v = (v < 0.75f) ? 0.f : v;
        float xn = (v - vmin) / denom;
        float d  = fmaxf(xn, c1);
        float tt = logf(d / (d - 0.01f));
        tt = tt * 31.0f / tmax;
        float r = rintf(tt);                 // round-half-even, matches jnp.round
        r = fminf(fmaxf(r, 0.f), 31.f);
        int ti = (int)r;
        cnt[ti * F_IN + f] += 1.0f;          // column private, no atomics
    }

#pragma unroll
    for (int t = 0; t < T_STEPS; ++t)
        out[(size_t)t * (B_SZ * F_IN) + (size_t)b * F_IN + f] =
            cnt[t * F_IN + f] * 0.015625f;   // / 64 (exact)
}

// ---------------------------------------------------------------------------
// C[m,n] = bias[n] + sum_k A[m,k] * W[n,k]
// A: (M_ROWS x K) row-major, W: (N x K) row-major (both K-contiguous).
// 64x64 block tile, BK=16, 256 threads, 4x4 outputs/thread, float4 loads.
// M=16384, N in {256,128}, K in {128,256} -> all divisible, no bounds checks.
// ---------------------------------------------------------------------------
#define BM 64
#define BN 64
#define BK 16

__global__ void gemm_bias_kernel(const float* __restrict__ A,
                                 const float* __restrict__ W,
                                 const float* __restrict__ bias,
                                 float* __restrict__ C,
                                 int N, int K) {
    __shared__ float As[BK][BM + 4];   // +4 pad keeps 16B alignment, fewer conflicts
    __shared__ float Bs[BK][BN + 4];

    int tid = threadIdx.x;             // 256 threads
    int tx = tid & 15;
    int ty = tid >> 4;
    int m0 = blockIdx.y * BM;
    int n0 = blockIdx.x * BN;

    int lr = tid >> 2;                 // 0..63 : tile row
    int lk = (tid & 3) * 4;            // 0,4,8,12 : k offset (float4)

    float acc[4][4];
#pragma unroll
    for (int i = 0; i < 4; ++i)
#pragma unroll
        for (int j = 0; j < 4; ++j) acc[i][j] = 0.f;

    const float* Aptr = A + (size_t)(m0 + lr) * K + lk;
    const float* Wptr = W + (size_t)(n0 + lr) * K + lk;

    for (int kt = 0; kt < K; kt += BK) {
        float4 av = *(const float4*)(Aptr + kt);
        float4 wv = *(const float4*)(Wptr + kt);
        As[lk + 0][lr] = av.x; As[lk + 1][lr] = av.y;
        As[lk + 2][lr] = av.z; As[lk + 3][lr] = av.w;
        Bs[lk + 0][lr] = wv.x; Bs[lk + 1][lr] = wv.y;
        Bs[lk + 2][lr] = wv.z; Bs[lk + 3][lr] = wv.w;
        __syncthreads();

#pragma unroll
        for (int k = 0; k < BK; ++k) {
            float4 a  = *(const float4*)&As[k][ty * 4];
            float4 bb = *(const float4*)&Bs[k][tx * 4];
            float ar[4] = {a.x, a.y, a.z, a.w};
            float br[4] = {bb.x, bb.y, bb.z, bb.w};
#pragma unroll
            for (int i = 0; i < 4; ++i)
#pragma unroll
                for (int j = 0; j < 4; ++j)
                    acc[i][j] = fmaf(ar[i], br[j], acc[i][j]);
        }
        __syncthreads();
    }

#pragma unroll
    for (int i = 0; i < 4; ++i) {
        int row = m0 + ty * 4 + i;
        float* cp = C + (size_t)row * N + n0 + tx * 4;
        const float* bp = bias + n0 + tx * 4;
        float4 o;
        o.x = acc[i][0] + bp[0];
        o.y = acc[i][1] + bp[1];
        o.z = acc[i][2] + bp[2];
        o.w = acc[i][3] + bp[3];
        *(float4*)cp = o;
    }
}

// ---------------------------------------------------------------------------
// LIF scan (reset-by-subtraction), snntorch Leaky semantics:
//   reset = (mem_prev - 1 > 0); mem = 0.9*mem + cur - reset; spk = (mem - 1 > 0)
// One thread per neuron (b,h); n = B*H per timestep. Loads fully unrolled.
// ---------------------------------------------------------------------------
__global__ void lif_scan_kernel(const float* __restrict__ cur,
                                float* __restrict__ spk, int n) {
    int i = blockIdx.x * blockDim.x + threadIdx.x;
    if (i >= n) return;
    float mem = 0.f;
#pragma unroll
    for (int t = 0; t < T_STEPS; ++t) {
        float c = cur[(size_t)t * n + i];
        float reset = (mem > 1.0f) ? 1.0f : 0.0f;
        mem = 0.9f * mem + c - reset;
        spk[(size_t)t * n + i] = (mem > 1.0f) ? 1.0f : 0.0f;
    }
}

// ---------------------------------------------------------------------------
extern "C" void kernel_launch(void* const* d_in, const int* in_sizes, int n_in,
                              void* d_out, int out_size) {
    const float* x  = (const float*)d_in[0];
    const float* W1 = (const float*)d_in[1];
    const float* b1 = (const float*)d_in[2];
    const float* W2 = (const float*)d_in[3];
    const float* b2 = (const float*)d_in[4];
    const float* W3 = (const float*)d_in[5];
    const float* b3 = (const float*)d_in[6];
    float* out = (float*)d_out;

    float *spk0, *cur, *spk1, *spk2;
    cudaGetSymbolAddress((void**)&spk0, g_spk0);
    cudaGetSymbolAddress((void**)&cur,  g_cur);
    cudaGetSymbolAddress((void**)&spk1, g_spk1);
    cudaGetSymbolAddress((void**)&spk2, g_spk2);

    // 1. encode
    encode_kernel<<<B_SZ, F_IN>>>(x, spk0);

    // 2. layer 1: GEMM (16384 x 128) @ (256 x 128)^T + scan
    {
        dim3 grid(H1 / BN, M_ROWS / BM);
        gemm_bias_kernel<<<grid, 256>>>(spk0, W1, b1, cur, H1, F_IN);
        int n = B_SZ * H1;
        lif_scan_kernel<<<(n + 255) / 256, 256>>>(cur, spk1, n);
    }
    // 3. layer 2: (16384 x 256) @ (256 x 256)^T + scan
    {
        dim3 grid(H2 / BN, M_ROWS / BM);
        gemm_bias_kernel<<<grid, 256>>>(spk1, W2, b2, cur, H2, H1);
        int n = B_SZ * H2;
        lif_scan_kernel<<<(n + 255) / 256, 256>>>(cur, spk2, n);
    }
    // 4. layer 3: (16384 x 256) @ (128 x 256)^T + scan -> d_out
    {
        dim3 grid(H3 / BN, M_ROWS / BM);
        gemm_bias_kernel<<<grid, 256>>>(spk2, W3, b3, cur, H3, H2);
        int n = B_SZ * H3;
        lif_scan_kernel<<<(n + 255) / 256, 256>>>(cur, out, n);
    }
}